// round 3
// baseline (speedup 1.0000x reference)
#include <cuda_runtime.h>
#include <stdint.h>

// Problem constants (fixed by the dataset)
#define BB   1024   // boards
#define NN2  361    // cells
#define MM   361    // history length
#define HASH_SLOTS 1024
#define HASH_MASK  1023
#define NTHREADS   256

__device__ __forceinline__ unsigned hash_fn(int v) {
    return (((unsigned)v) * 2654435761u) >> 22;   // top 10 bits -> [0,1024)
}

__global__ __launch_bounds__(NTHREADS)
void superko_kernel(const int* __restrict__ ZposT,           // [3, N2]
                    const int* __restrict__ current_player,  // [B]
                    const int* __restrict__ current_hash,    // [B]
                    const int* __restrict__ hash_history,    // [B, M]
                    const int* __restrict__ move_count,      // [B]
                    const int* __restrict__ legal,           // [B, N2] bool (any 4-byte repr; 0 == false)
                    const int* __restrict__ sidx,            // [K]
                    const int* __restrict__ sptr,            // [R+1]
                    const int* __restrict__ gptr,            // [B+1]
                    const int* __restrict__ cap,             // [B, N2, 4]
                    float* __restrict__ out)                 // [B, N2] bool as float32
{
    __shared__ int hset[HASH_SLOTS];
    __shared__ int z_empty[NN2];
    __shared__ int z_color[NN2];   // current player's color row
    __shared__ int gxor[64];       // per-board group XOR deltas (local index)

    const int b   = blockIdx.x;
    const int tid = threadIdx.x;

    // --- init hash set + cache zobrist rows ---
    const int player = current_player[b];
    const int* ze = ZposT;                                    // row 0: empty
    const int* zc = ZposT + (player == 0 ? NN2 : 2 * NN2);    // row 1+player
    const int* zo = ZposT + (player == 0 ? 2 * NN2 : NN2);    // row 1+(1-player)

    #pragma unroll
    for (int i = tid; i < HASH_SLOTS; i += NTHREADS) hset[i] = -1;
    for (int i = tid; i < NN2; i += NTHREADS) {
        z_empty[i] = ze[i];
        z_color[i] = zc[i];
    }
    __syncthreads();

    // --- insert history[0:mc) into SMEM hash set ---
    int mc = move_count[b];
    if (mc > MM) mc = MM;
    if (mc < 0)  mc = 0;
    const int* hist = hash_history + (long long)b * MM;
    for (int t = tid; t < mc; t += NTHREADS) {
        int v = hist[t];
        unsigned h = hash_fn(v) & HASH_MASK;
        while (true) {
            int prev = atomicCAS(&hset[h], -1, v);
            if (prev == -1 || prev == v) break;
            h = (h + 1) & HASH_MASK;
        }
    }

    // --- per-group removal deltas (plain XOR == per-bit parity) ---
    const int gstart = gptr[b];
    const int ng     = gptr[b + 1] - gstart;
    for (int g = tid; g < ng; g += NTHREADS) {
        int s0 = sptr[gstart + g];
        int s1 = sptr[gstart + g + 1];
        int x  = 0;
        for (int s = s0; s < s1; ++s) {
            int c = sidx[s];
            x ^= zo[c] ^ z_empty[c];
        }
        if (g < 64) gxor[g] = x;
    }
    __syncthreads();

    // --- per-cell candidate hash + repeat check ---
    const int ch = current_hash[b];
    const int4* cap4 = (const int4*)(cap + (long long)b * NN2 * 4);
    const int* lg = legal + (long long)b * NN2;
    float* ob = out + (long long)b * NN2;

    for (int j = tid; j < NN2; j += NTHREADS) {
        int4 c4 = cap4[j];
        int cd = 0;
        if (c4.x >= 0) cd ^= gxor[c4.x];
        if (c4.y >= 0) cd ^= gxor[c4.y];
        if (c4.z >= 0) cd ^= gxor[c4.z];
        if (c4.w >= 0) cd ^= gxor[c4.w];

        int cand = ch ^ (z_empty[j] ^ z_color[j]) ^ cd;

        bool found = false;
        unsigned h = hash_fn(cand) & HASH_MASK;
        while (true) {
            int v = hset[h];
            if (v == cand) { found = true; break; }
            if (v == -1) break;
            h = (h + 1) & HASH_MASK;
        }
        // legal is a bool array: 0 encodes false for both int32 and float32 reps
        ob[j] = (lg[j] != 0 && !found) ? 1.0f : 0.0f;
    }
}

extern "C" void kernel_launch(void* const* d_in, const int* in_sizes, int n_in,
                              void* d_out, int out_size) {
    const int* ZposT        = (const int*)d_in[0];
    const int* cur_player   = (const int*)d_in[1];
    const int* cur_hash     = (const int*)d_in[2];
    const int* hash_hist    = (const int*)d_in[3];
    const int* mv_count     = (const int*)d_in[4];
    const int* lg           = (const int*)d_in[5];
    const int* sidx         = (const int*)d_in[6];
    const int* sptr         = (const int*)d_in[7];
    const int* gptr         = (const int*)d_in[8];
    const int* cap          = (const int*)d_in[9];
    // d_in[10] = scale (unused by the reference output)

    float* out = (float*)d_out;

    superko_kernel<<<BB, NTHREADS>>>(ZposT, cur_player, cur_hash, hash_hist,
                                     mv_count, lg, sidx, sptr, gptr, cap, out);
}

// round 4
// speedup vs baseline: 1.1279x; 1.1279x over previous
#include <cuda_runtime.h>
#include <stdint.h>

// Problem constants (fixed by the dataset)
#define BB   1024   // boards
#define NN2  361    // cells
#define MM   361    // history length
#define HASH_SLOTS 1024
#define HASH_MASK  1023
#define NTHREADS   256
#define MAX_STONES 256  // per board (dataset: G=8 * S=16 = 128)

__device__ __forceinline__ unsigned hash_fn(int v) {
    return (((unsigned)v) * 2654435761u) >> 22;   // top 10 bits -> [0,1024)
}

__global__ __launch_bounds__(NTHREADS)
void superko_kernel(const int* __restrict__ ZposT,           // [3, N2]
                    const int* __restrict__ current_player,  // [B]
                    const int* __restrict__ current_hash,    // [B]
                    const int* __restrict__ hash_history,    // [B, M]
                    const int* __restrict__ move_count,      // [B]
                    const int* __restrict__ legal,           // [B, N2] bool (4-byte; 0 == false)
                    const int* __restrict__ sidx,            // [K]
                    const int* __restrict__ sptr,            // [R+1]
                    const int* __restrict__ gptr,            // [B+1]
                    const int* __restrict__ cap,             // [B, N2, 4]
                    float* __restrict__ out)                 // [B, N2] bool as float32
{
    __shared__ int hset[HASH_SLOTS];
    __shared__ int pd_b[NN2];          // z_empty ^ z_black  (placement delta if player==0)
    __shared__ int pd_w[NN2];          // z_empty ^ z_white  (placement delta if player==1)
    __shared__ int sdelta[MAX_STONES]; // per-stone removal delta (opponent color)
    __shared__ int gxor[64];           // per-group removal XOR

    const int b   = blockIdx.x;
    const int tid = threadIdx.x;

    // ================= PHASE 0: fire every independent global load =================
    // Scalars (L1-broadcast; no cross-dependency)
    const int player = __ldg(&current_player[b]);
    int mc           = __ldg(&move_count[b]);
    const int ch     = __ldg(&current_hash[b]);
    if (mc > MM) mc = MM;
    if (mc < 0)  mc = 0;

    // Prefetch capture slots + legal (the dominant traffic) into registers
    const int4* cap4 = (const int4*)(cap + (long long)b * NN2 * 4);
    const int*  lg   = legal + (long long)b * NN2;
    int4 c4_0 = cap4[tid];
    int  lg_0 = lg[tid];
    int4 c4_1 = make_int4(-1, -1, -1, -1);
    int  lg_1 = 0;
    if (tid + NTHREADS < NN2) {
        c4_1 = cap4[tid + NTHREADS];
        lg_1 = lg[tid + NTHREADS];
    }

    // Prefetch history values (insert later, once hset is initialized)
    const int* hist = hash_history + (long long)b * MM;
    int hv0 = hist[tid];
    int hv1 = (tid + NTHREADS < MM) ? hist[tid + NTHREADS] : 0;

    // Init hash set
    #pragma unroll
    for (int i = tid; i < HASH_SLOTS; i += NTHREADS) hset[i] = -1;

    // Build both placement-delta rows (independent of `player`)
    for (int i = tid; i < NN2; i += NTHREADS) {
        int ze = ZposT[i];
        pd_b[i] = ze ^ ZposT[NN2 + i];
        pd_w[i] = ze ^ ZposT[2 * NN2 + i];
    }

    // Per-stone removal deltas, coalesced (opponent = 1 - player)
    const int gstart     = gptr[b];
    const int ng         = gptr[b + 1] - gstart;
    const int stone_base = sptr[gstart];
    int nstones          = sptr[gstart + ng] - stone_base;
    if (nstones > MAX_STONES) nstones = MAX_STONES;
    if (tid < nstones) {
        int c  = sidx[stone_base + tid];
        int ze = ZposT[c];
        int db = ze ^ ZposT[NN2 + c];       // removal delta if opponent is black
        int dw = ze ^ ZposT[2 * NN2 + c];   // removal delta if opponent is white
        sdelta[tid] = (player == 0) ? dw : db;   // opp = 1 - player
    }

    __syncthreads();

    // ================= PHASE 1: populate hash set + group XORs =================
    if (tid < mc) {
        unsigned h = hash_fn(hv0) & HASH_MASK;
        while (true) {
            int prev = atomicCAS(&hset[h], -1, hv0);
            if (prev == -1 || prev == hv0) break;
            h = (h + 1) & HASH_MASK;
        }
    }
    if (tid + NTHREADS < mc) {
        unsigned h = hash_fn(hv1) & HASH_MASK;
        while (true) {
            int prev = atomicCAS(&hset[h], -1, hv1);
            if (prev == -1 || prev == hv1) break;
            h = (h + 1) & HASH_MASK;
        }
    }

    if (tid < ng && tid < 64) {
        int s0 = sptr[gstart + tid] - stone_base;
        int s1 = sptr[gstart + tid + 1] - stone_base;
        if (s1 > nstones) s1 = nstones;
        int x = 0;
        for (int s = s0; s < s1; ++s) x ^= sdelta[s];
        gxor[tid] = x;
    }

    __syncthreads();

    // ================= PHASE 2: per-cell candidate + probe =================
    const int* pd = (player == 0) ? pd_b : pd_w;
    float* ob = out + (long long)b * NN2;

    {
        int cd = 0;
        if (c4_0.x >= 0) cd ^= gxor[c4_0.x];
        if (c4_0.y >= 0) cd ^= gxor[c4_0.y];
        if (c4_0.z >= 0) cd ^= gxor[c4_0.z];
        if (c4_0.w >= 0) cd ^= gxor[c4_0.w];
        int cand = ch ^ pd[tid] ^ cd;

        bool found = false;
        unsigned h = hash_fn(cand) & HASH_MASK;
        while (true) {
            int v = hset[h];
            if (v == -1) break;            // empty slot first: -1 never stored
            if (v == cand) { found = true; break; }
            h = (h + 1) & HASH_MASK;
        }
        ob[tid] = (lg_0 != 0 && !found) ? 1.0f : 0.0f;
    }

    if (tid + NTHREADS < NN2) {
        int j = tid + NTHREADS;
        int cd = 0;
        if (c4_1.x >= 0) cd ^= gxor[c4_1.x];
        if (c4_1.y >= 0) cd ^= gxor[c4_1.y];
        if (c4_1.z >= 0) cd ^= gxor[c4_1.z];
        if (c4_1.w >= 0) cd ^= gxor[c4_1.w];
        int cand = ch ^ pd[j] ^ cd;

        bool found = false;
        unsigned h = hash_fn(cand) & HASH_MASK;
        while (true) {
            int v = hset[h];
            if (v == -1) break;
            if (v == cand) { found = true; break; }
            h = (h + 1) & HASH_MASK;
        }
        ob[j] = (lg_1 != 0 && !found) ? 1.0f : 0.0f;
    }
}

extern "C" void kernel_launch(void* const* d_in, const int* in_sizes, int n_in,
                              void* d_out, int out_size) {
    const int* ZposT        = (const int*)d_in[0];
    const int* cur_player   = (const int*)d_in[1];
    const int* cur_hash     = (const int*)d_in[2];
    const int* hash_hist    = (const int*)d_in[3];
    const int* mv_count     = (const int*)d_in[4];
    const int* lg           = (const int*)d_in[5];
    const int* sidx         = (const int*)d_in[6];
    const int* sptr         = (const int*)d_in[7];
    const int* gptr         = (const int*)d_in[8];
    const int* cap          = (const int*)d_in[9];
    // d_in[10] = scale (unused by the reference output)

    float* out = (float*)d_out;

    superko_kernel<<<BB, NTHREADS>>>(ZposT, cur_player, cur_hash, hash_hist,
                                     mv_count, lg, sidx, sptr, gptr, cap, out);
}

// round 5
// speedup vs baseline: 1.1582x; 1.0269x over previous
#include <cuda_runtime.h>
#include <stdint.h>

// Problem constants (fixed by the dataset)
#define BB   1024   // boards
#define NN2  361    // cells
#define MM   361    // history length
#define HASH_SLOTS 1024
#define HASH_MASK  1023
#define NT   128    // threads per CTA (4 warps -> deep CTA interleave, 1 wave)
#define MAX_STONES 256

__device__ __forceinline__ unsigned hash_fn(int v) {
    return (((unsigned)v) * 2654435761u) >> 22;   // top 10 bits -> [0,1024)
}

__global__ __launch_bounds__(NT)
void superko_kernel(const int* __restrict__ ZposT,           // [3, N2]
                    const int* __restrict__ current_player,  // [B]
                    const int* __restrict__ current_hash,    // [B]
                    const int* __restrict__ hash_history,    // [B, M]
                    const int* __restrict__ move_count,      // [B]
                    const int* __restrict__ legal,           // [B, N2] bool (4B; 0 == false)
                    const int* __restrict__ sidx,            // [K]
                    const int* __restrict__ sptr,            // [R+1]
                    const int* __restrict__ gptr,            // [B+1]
                    const int* __restrict__ cap,             // [B, N2, 4]
                    float* __restrict__ out)                 // [B, N2] bool as float32
{
    __shared__ int hset[HASH_SLOTS];
    __shared__ int sdelta[MAX_STONES];
    __shared__ int gxor[64];

    const int b   = blockIdx.x;
    const int tid = threadIdx.x;

    // ---------------- PHASE 0: fire every independent global load ----------------
    const int player = __ldg(&current_player[b]);
    int mc           = __ldg(&move_count[b]);
    const int ch     = __ldg(&current_hash[b]);
    if (mc > MM) mc = MM;
    if (mc < 0)  mc = 0;

    const int4* cap4 = (const int4*)(cap + (long long)b * NN2 * 4);
    const int*  lg   = legal + (long long)b * NN2;
    const int*  zcRow = ZposT + (player == 0 ? NN2 : 2 * NN2);  // current player's color
    const int*  zoRow = ZposT + (player == 0 ? 2 * NN2 : NN2);  // opponent's color

    const int j0 = tid, j1 = tid + NT, j2 = tid + 2 * NT;

    // cell 0 (always valid: NT=128 <= 361)
    int4 c4_0 = cap4[j0];
    int  lg_0 = lg[j0];
    int  pd_0 = ZposT[j0] ^ zcRow[j0];
    // cell 1 (j1 < 361 always: 255 < 361)
    int4 c4_1 = cap4[j1];
    int  lg_1 = lg[j1];
    int  pd_1 = ZposT[j1] ^ zcRow[j1];
    // cell 2 (valid iff tid < 105)
    int4 c4_2 = make_int4(-1, -1, -1, -1);
    int  lg_2 = 0, pd_2 = 0;
    const bool has2 = (j2 < NN2);
    if (has2) {
        c4_2 = cap4[j2];
        lg_2 = lg[j2];
        pd_2 = ZposT[j2] ^ zcRow[j2];
    }

    // history prefetch (3 entries/thread)
    const int* hist = hash_history + (long long)b * MM;
    int hv0 = hist[j0];
    int hv1 = hist[j1];
    int hv2 = has2 ? hist[j2] : 0;

    // init hash set (8 stores/thread)
    #pragma unroll
    for (int i = tid; i < HASH_SLOTS; i += NT) hset[i] = -1;

    // per-stone removal deltas (1 stone/thread in the dataset: 128 stones)
    const int gstart     = gptr[b];
    const int ng         = gptr[b + 1] - gstart;
    const int stone_base = sptr[gstart];
    int nstones          = sptr[gstart + ng] - stone_base;
    if (nstones > MAX_STONES) nstones = MAX_STONES;
    for (int s = tid; s < nstones; s += NT) {
        int c = sidx[stone_base + s];
        sdelta[s] = ZposT[c] ^ zoRow[c];
    }

    __syncthreads();

    // ---------------- PHASE 1: populate hash set + group XORs ----------------
    if (j0 < mc) {
        unsigned h = hash_fn(hv0) & HASH_MASK;
        while (true) {
            int prev = atomicCAS(&hset[h], -1, hv0);
            if (prev == -1 || prev == hv0) break;
            h = (h + 1) & HASH_MASK;
        }
    }
    if (j1 < mc) {
        unsigned h = hash_fn(hv1) & HASH_MASK;
        while (true) {
            int prev = atomicCAS(&hset[h], -1, hv1);
            if (prev == -1 || prev == hv1) break;
            h = (h + 1) & HASH_MASK;
        }
    }
    if (j2 < mc) {
        unsigned h = hash_fn(hv2) & HASH_MASK;
        while (true) {
            int prev = atomicCAS(&hset[h], -1, hv2);
            if (prev == -1 || prev == hv2) break;
            h = (h + 1) & HASH_MASK;
        }
    }

    if (tid < ng && tid < 64) {
        int s0 = sptr[gstart + tid] - stone_base;
        int s1 = sptr[gstart + tid + 1] - stone_base;
        if (s1 > nstones) s1 = nstones;
        int x = 0;
        for (int s = s0; s < s1; ++s) x ^= sdelta[s];
        gxor[tid] = x;
    }

    __syncthreads();

    // ---------------- PHASE 2: per-cell candidate + probe ----------------
    float* ob = out + (long long)b * NN2;

    {
        int cd = 0;
        if (c4_0.x >= 0) cd ^= gxor[c4_0.x];
        if (c4_0.y >= 0) cd ^= gxor[c4_0.y];
        if (c4_0.z >= 0) cd ^= gxor[c4_0.z];
        if (c4_0.w >= 0) cd ^= gxor[c4_0.w];
        int cand = ch ^ pd_0 ^ cd;
        bool found = false;
        unsigned h = hash_fn(cand) & HASH_MASK;
        while (true) {
            int v = hset[h];
            if (v == -1) break;
            if (v == cand) { found = true; break; }
            h = (h + 1) & HASH_MASK;
        }
        ob[j0] = (lg_0 != 0 && !found) ? 1.0f : 0.0f;
    }
    {
        int cd = 0;
        if (c4_1.x >= 0) cd ^= gxor[c4_1.x];
        if (c4_1.y >= 0) cd ^= gxor[c4_1.y];
        if (c4_1.z >= 0) cd ^= gxor[c4_1.z];
        if (c4_1.w >= 0) cd ^= gxor[c4_1.w];
        int cand = ch ^ pd_1 ^ cd;
        bool found = false;
        unsigned h = hash_fn(cand) & HASH_MASK;
        while (true) {
            int v = hset[h];
            if (v == -1) break;
            if (v == cand) { found = true; break; }
            h = (h + 1) & HASH_MASK;
        }
        ob[j1] = (lg_1 != 0 && !found) ? 1.0f : 0.0f;
    }
    if (has2) {
        int cd = 0;
        if (c4_2.x >= 0) cd ^= gxor[c4_2.x];
        if (c4_2.y >= 0) cd ^= gxor[c4_2.y];
        if (c4_2.z >= 0) cd ^= gxor[c4_2.z];
        if (c4_2.w >= 0) cd ^= gxor[c4_2.w];
        int cand = ch ^ pd_2 ^ cd;
        bool found = false;
        unsigned h = hash_fn(cand) & HASH_MASK;
        while (true) {
            int v = hset[h];
            if (v == -1) break;
            if (v == cand) { found = true; break; }
            h = (h + 1) & HASH_MASK;
        }
        ob[j2] = (lg_2 != 0 && !found) ? 1.0f : 0.0f;
    }
}

extern "C" void kernel_launch(void* const* d_in, const int* in_sizes, int n_in,
                              void* d_out, int out_size) {
    const int* ZposT        = (const int*)d_in[0];
    const int* cur_player   = (const int*)d_in[1];
    const int* cur_hash     = (const int*)d_in[2];
    const int* hash_hist    = (const int*)d_in[3];
    const int* mv_count     = (const int*)d_in[4];
    const int* lg           = (const int*)d_in[5];
    const int* sidx         = (const int*)d_in[6];
    const int* sptr         = (const int*)d_in[7];
    const int* gptr         = (const int*)d_in[8];
    const int* cap          = (const int*)d_in[9];
    // d_in[10] = scale (unused by the reference output)

    float* out = (float*)d_out;

    superko_kernel<<<BB, NT>>>(ZposT, cur_player, cur_hash, hash_hist,
                               mv_count, lg, sidx, sptr, gptr, cap, out);
}